// round 15
// baseline (speedup 1.0000x reference)
#include <cuda_runtime.h>
#include <string.h>

// RoutingLayer: capsule dynamic routing.
//   N=50000, M=32 neighbors, D=128 = K(8) x 16, max_iter=6.
// Inputs: x fp32 [N,128], neighbors int32 [N*32], max_iter (fixed 6).
// Output: u fp32 [N,128].

#define N_NODES 50000
#define M_NB    32
#define D_DIM   128
#define K_CAPS  8
#define MAX_IT  6
#define EPS_N   1e-12f
#define FULLM   0xffffffffu
#define L2E     1.44269504088896f

typedef unsigned long long u64;

// ---- f32x2 packed-math helpers (ptxas never auto-fuses FFMA2 from C++) ----
__device__ __forceinline__ u64 pack2(float a, float b) {
    u64 r; asm("mov.b64 %0,{%1,%2};" : "=l"(r) : "f"(a), "f"(b)); return r;
}
__device__ __forceinline__ float2 unpack2(u64 v) {
    float2 f; asm("mov.b64 {%0,%1},%2;" : "=f"(f.x), "=f"(f.y) : "l"(v)); return f;
}
__device__ __forceinline__ u64 fma2(u64 a, u64 b, u64 c) {
    u64 d; asm("fma.rn.f32x2 %0,%1,%2,%3;" : "=l"(d) : "l"(a), "l"(b), "l"(c)); return d;
}
__device__ __forceinline__ u64 mul2(u64 a, u64 b) {
    u64 d; asm("mul.rn.f32x2 %0,%1,%2;" : "=l"(d) : "l"(a), "l"(b)); return d;
}
__device__ __forceinline__ u64 add2(u64 a, u64 b) {
    u64 d; asm("add.rn.f32x2 %0,%1,%2;" : "=l"(d) : "l"(a), "l"(b)); return d;
}
__device__ __forceinline__ float ex2f(float x) {
    float y; asm("ex2.approx.f32 %0,%1;" : "=f"(y) : "f"(x)); return y;
}

// Scratch: per-capsule L2-normalized x.
__device__ float g_xn[(size_t)N_NODES * D_DIM];

// ---------------------------------------------------------------------------
// Kernel 1: per-capsule normalize x into g_xn (4 lanes per 16-wide capsule).
// ---------------------------------------------------------------------------
__global__ void __launch_bounds__(256) caps_normalize_kernel(const float* __restrict__ x)
{
    int c = blockIdx.x * 64 + (threadIdx.x >> 2);
    int j = threadIdx.x & 3;
    if (c >= N_NODES * K_CAPS) return;

    const float4 v = __ldg(reinterpret_cast<const float4*>(x + (size_t)c * 16 + 4 * j));
    float ss = v.x * v.x + v.y * v.y + v.z * v.z + v.w * v.w;
    ss += __shfl_xor_sync(FULLM, ss, 1);
    ss += __shfl_xor_sync(FULLM, ss, 2);
    float inv = 1.0f / fmaxf(sqrtf(ss), EPS_N);
    float4 o = make_float4(v.x * inv, v.y * inv, v.z * inv, v.w * inv);
    *reinterpret_cast<float4*>(g_xn + (size_t)c * 16 + 4 * j) = o;
}

// ---------------------------------------------------------------------------
// Kernel 2: routing. One 128-thread CTA per node, 9 CTAs/SM (regs <= 56).
//   warp w owns m {8w..8w+7}; lane owns d-slice [4l..4l+3] (z as b64 pairs).
//   Renorm folded into exp constant: e = ex2((z.v) * inv*log2e).
//   Dot FMAs interleaved with RS xor1 shuffles (pipe overlap, lower reg peak).
//   Accumulators split into 2 chains each (FFMA2 depth 4).
//   Softmax denom via 2-value reduce-scatter; p allgather via 384B smem.
//   Split-d reduce: warp w owns d in [32w,32w+32), one d/lane.
// ---------------------------------------------------------------------------
__global__ void __launch_bounds__(128, 9) routing_kernel(const int* __restrict__ neighbors,
                                                         float* __restrict__ out)
{
    const int n     = blockIdx.x;
    const int tid   = threadIdx.x;
    const int w     = tid >> 5;
    const int lane  = tid & 31;
    const int c     = lane & 3;          // m-slot within reduce-scatter
    const bool b0   = (lane & 1) != 0;
    const bool b1   = (lane & 2) != 0;
    const bool b2   = (lane & 4) != 0;
    const int dmine = 32 * w + lane;     // this thread's d in reduce phase

    __shared__ float part[4 * 132];      // cross-warp partials (padded rows)
    __shared__ float u_s[D_DIM];         // raw v transpose buffer
    __shared__ float pex[4 * 96];        // per-warp p exchange: [k][q], stride 12

    // hoisted pex row base for this thread: row = capsule kk = lane>>2
    float* const mypex = pex + w * 96 + (lane >> 2) * 12;

    // Warp w's 8 neighbor indices: lanes 0..7 load, distribute via shuffle.
    int r_my = 0;
    if (lane < 8) r_my = neighbors[(size_t)n * M_NB + w * 8 + lane];

    // Gather z rows as b64 pairs (zl = d[4l..4l+1], zh = d[4l+2..4l+3]).
    u64 zl[8], zh[8];
#pragma unroll
    for (int q = 0; q < 8; q++) {
        int r = __shfl_sync(FULLM, r_my, q);
        if ((unsigned)r < (unsigned)N_NODES) {
            uint4 t = __ldg(reinterpret_cast<const uint4*>(g_xn + (size_t)r * D_DIM + 4 * lane));
            ulonglong2 zz; memcpy(&zz, &t, 16);
            zl[q] = zz.x; zh[q] = zz.y;
        } else {
            zl[q] = 0ull; zh[q] = 0ull;  // padding row (index == N)
        }
    }

    const float xcs = __ldg(g_xn + (size_t)n * D_DIM + dmine);

    u64 ul, uh;   // RAW v for this lane's d-slice, packed

    // ---- iteration 0: p = 1/8 uniformly; store raw v (no renorm) ----
    {
        u64 a0 = 0ull, a1 = 0ull;
#pragma unroll
        for (int q = 0; q < 8; q++) { a0 = add2(a0, zl[q]); a1 = add2(a1, zh[q]); }
        const u64 eighth = pack2(0.125f, 0.125f);
        a0 = mul2(a0, eighth); a1 = mul2(a1, eighth);

        *reinterpret_cast<ulonglong2*>(&part[w * 132 + 4 * lane]) = make_ulonglong2(a0, a1);
        __syncthreads();

        float v = xcs;
#pragma unroll
        for (int w2 = 0; w2 < 4; w2++) v += part[w2 * 132 + dmine];
        u_s[dmine] = v;                  // raw, unnormalized
        __syncthreads();

        uint4 t = *reinterpret_cast<const uint4*>(&u_s[4 * lane]);
        ulonglong2 uu; memcpy(&uu, &t, 16);
        ul = uu.x; uh = uu.y;
    }

    // ---- iterations 1..5 ----
#pragma unroll
    for (int it = 1; it < MAX_IT; it++) {
        // per-capsule ||v||^2 -> li = rsqrt * log2e (feeds ex2 directly)
        float li;
        {
            float2 f = unpack2(fma2(ul, ul, mul2(uh, uh)));
            float ssq = f.x + f.y;
            ssq += __shfl_xor_sync(FULLM, ssq, 1);
            ssq += __shfl_xor_sync(FULLM, ssq, 2);
            li = rsqrtf(fmaxf(ssq, EPS_N * EPS_N)) * L2E;
        }

        // dots interleaved with RS xor1: first half
        float a0, a1, a2, a3;
        {
            float2 f;
            float sp0, sp1, sp2, sp3;
            f = unpack2(fma2(zl[0], ul, mul2(zh[0], uh))); sp0 = f.x + f.y;
            f = unpack2(fma2(zl[1], ul, mul2(zh[1], uh))); sp1 = f.x + f.y;
            f = unpack2(fma2(zl[2], ul, mul2(zh[2], uh))); sp2 = f.x + f.y;
            f = unpack2(fma2(zl[3], ul, mul2(zh[3], uh))); sp3 = f.x + f.y;
            float sd, kp;
            sd = b0 ? sp0 : sp1; kp = b0 ? sp1 : sp0;
            a0 = kp + __shfl_xor_sync(FULLM, sd, 1);
            sd = b0 ? sp2 : sp3; kp = b0 ? sp3 : sp2;
            a1 = kp + __shfl_xor_sync(FULLM, sd, 1);
            // second half overlaps the first xor1 latencies
            f = unpack2(fma2(zl[4], ul, mul2(zh[4], uh))); sp0 = f.x + f.y;
            f = unpack2(fma2(zl[5], ul, mul2(zh[5], uh))); sp1 = f.x + f.y;
            f = unpack2(fma2(zl[6], ul, mul2(zh[6], uh))); sp2 = f.x + f.y;
            f = unpack2(fma2(zl[7], ul, mul2(zh[7], uh))); sp3 = f.x + f.y;
            sd = b0 ? sp0 : sp1; kp = b0 ? sp1 : sp0;
            a2 = kp + __shfl_xor_sync(FULLM, sd, 1);
            sd = b0 ? sp2 : sp3; kp = b0 ? sp3 : sp2;
            a3 = kp + __shfl_xor_sync(FULLM, sd, 1);
        }
        // reduce-scatter over xor2: s_i = full 16-dot for q = 4i + c
        float s0, s1;
        {
            float sd, kp;
            sd = b1 ? a0 : a1; kp = b1 ? a1 : a0;
            s0 = kp + __shfl_xor_sync(FULLM, sd, 2);
            sd = b1 ? a2 : a3; kp = b1 ? a3 : a2;
            s1 = kp + __shfl_xor_sync(FULLM, sd, 2);
        }

        // e = 2^{ (z.v) * inv * log2e }  (renorm folded; |s*inv| <= 1)
        float e0 = ex2f(s0 * li);
        float e1 = ex2f(s1 * li);

        // softmax denominators over k (8 lanes, stride 4) via 2-value RS
        float t0, t1;
        {
            float sd = b2 ? e0 : e1;
            float kp = b2 ? e1 : e0;
            float g  = kp + __shfl_xor_sync(FULLM, sd, 4);  // partial t_{b2}
            g += __shfl_xor_sync(FULLM, g, 8);
            g += __shfl_xor_sync(FULLM, g, 16);             // full t_{b2}
            float h = __shfl_xor_sync(FULLM, g, 4);         // partner's t
            t0 = b2 ? h : g;
            t1 = b2 ? g : h;
        }

        // allgather p via smem: row kk holds p for q = 0..7 of this warp
        mypex[c]     = __fdividef(e0, t0);   // p[q = c,     k = kk]
        mypex[4 + c] = __fdividef(e1, t1);   // p[q = 4 + c, k = kk]
        __syncwarp();
        const float4 lo = *reinterpret_cast<const float4*>(mypex);      // p[q=0..3]
        const float4 hi = *reinterpret_cast<const float4*>(mypex + 4);  // p[q=4..7]

        // weighted accumulation (f32x2), 2 chains per accumulator (depth 4)
        u64 acc0, acc1;
        {
            u64 pp;
            u64 a0a = 0ull, a0b = 0ull, a1a = 0ull, a1b = 0ull;
            pp = pack2(lo.x, lo.x); a0a = fma2(zl[0], pp, a0a); a1a = fma2(zh[0], pp, a1a);
            pp = pack2(lo.y, lo.y); a0b = fma2(zl[1], pp, a0b); a1b = fma2(zh[1], pp, a1b);
            pp = pack2(lo.z, lo.z); a0a = fma2(zl[2], pp, a0a); a1a = fma2(zh[2], pp, a1a);
            pp = pack2(lo.w, lo.w); a0b = fma2(zl[3], pp, a0b); a1b = fma2(zh[3], pp, a1b);
            pp = pack2(hi.x, hi.x); a0a = fma2(zl[4], pp, a0a); a1a = fma2(zh[4], pp, a1a);
            pp = pack2(hi.y, hi.y); a0b = fma2(zl[5], pp, a0b); a1b = fma2(zh[5], pp, a1b);
            pp = pack2(hi.z, hi.z); a0a = fma2(zl[6], pp, a0a); a1a = fma2(zh[6], pp, a1a);
            pp = pack2(hi.w, hi.w); a0b = fma2(zl[7], pp, a0b); a1b = fma2(zh[7], pp, a1b);
            acc0 = add2(a0a, a0b);
            acc1 = add2(a1a, a1b);
        }

        *reinterpret_cast<ulonglong2*>(&part[w * 132 + 4 * lane]) = make_ulonglong2(acc0, acc1);
        __syncthreads();

        // split-d reduce: this thread owns d = dmine
        float v = xcs;
#pragma unroll
        for (int w2 = 0; w2 < 4; w2++) v += part[w2 * 132 + dmine];

        if (it < MAX_IT - 1) {
            u_s[dmine] = v;              // raw v; normalization folded into dots
            __syncthreads();
            uint4 t = *reinterpret_cast<const uint4*>(&u_s[4 * lane]);
            ulonglong2 uu; memcpy(&uu, &t, 16);
            ul = uu.x; uh = uu.y;
        } else {
            // last iteration: reference leaves u unnormalized; write result
            out[(size_t)n * D_DIM + dmine] = v;
        }
    }
}

// ---------------------------------------------------------------------------
extern "C" void kernel_launch(void* const* d_in, const int* in_sizes, int n_in,
                              void* d_out, int out_size)
{
    const float* x   = (const float*)d_in[0];
    const int*   nb  = (const int*)d_in[1];
    float*       out = (float*)d_out;
    (void)in_sizes; (void)n_in; (void)out_size;

    int caps   = N_NODES * K_CAPS;
    int blocks = (caps + 63) / 64;
    caps_normalize_kernel<<<blocks, 256>>>(x);

    routing_kernel<<<N_NODES, 128>>>(nb, out);
}